// round 1
// baseline (speedup 1.0000x reference)
#include <cuda_runtime.h>
#include <math.h>
#include <float.h>

#define BS    4096
#define LSEQ  200
#define DDIM  64
#define KCAPS 4
#define VOCAB 100000
#define HPS   68   // hisP smem row stride in floats (padding for bank-conflict-free dual access)

// Scratch (allocation-free: device globals)
__device__ float g_ES[VOCAB * DDIM];            // 25.6 MB: E @ S, row 0 zeroed
__device__ float g_caps[BS * KCAPS * DDIM];     // 4 MB: routing output

// ---------------------------------------------------------------------------
// Kernel 1: ES = E @ S  (100000x64 @ 64x64), ES[0,:] = 0
// 256 threads, tile 256 rows, per-thread 8x8 register tile.
// ---------------------------------------------------------------------------
__global__ __launch_bounds__(256) void k_es(const float* __restrict__ E,
                                            const float* __restrict__ S) {
    extern __shared__ float sm[];
    float* Ssm = sm;                 // 64*64
    float* Esm = sm + 64 * 64;       // 256*65 (pad 65 -> conflict-free column reads)
    const int tid = threadIdx.x;
    const int v0 = blockIdx.x * 256;

    for (int i = tid; i < 64 * 64; i += 256) Ssm[i] = S[i];
    for (int i = tid; i < 256 * 64; i += 256) {
        int r = i >> 6, e = i & 63;
        int v = v0 + r;
        Esm[r * 65 + e] = (v < VOCAB) ? E[v * 64 + e] : 0.f;
    }
    __syncthreads();

    const int vg = tid >> 3;   // 0..31 -> 8 rows each
    const int dg = tid & 7;    // 0..7  -> 8 cols each
    float acc[8][8];
#pragma unroll
    for (int r = 0; r < 8; r++)
#pragma unroll
        for (int c = 0; c < 8; c++) acc[r][c] = 0.f;

#pragma unroll 2
    for (int e = 0; e < 64; e++) {
        float Ev[8], Sv[8];
#pragma unroll
        for (int r = 0; r < 8; r++) Ev[r] = Esm[(vg * 8 + r) * 65 + e];
#pragma unroll
        for (int c = 0; c < 8; c++) Sv[c] = Ssm[e * 64 + dg * 8 + c];
#pragma unroll
        for (int r = 0; r < 8; r++)
#pragma unroll
            for (int c = 0; c < 8; c++) acc[r][c] = fmaf(Ev[r], Sv[c], acc[r][c]);
    }

#pragma unroll
    for (int r = 0; r < 8; r++) {
        int v = v0 + vg * 8 + r;
        if (v >= VOCAB) continue;
        if (v == 0) {
#pragma unroll
            for (int c = 0; c < 8; c++) acc[r][c] = 0.f;  // padding_idx row
        }
        float4 o0 = make_float4(acc[r][0], acc[r][1], acc[r][2], acc[r][3]);
        float4 o1 = make_float4(acc[r][4], acc[r][5], acc[r][6], acc[r][7]);
        *(float4*)&g_ES[v * 64 + dg * 8 + 0] = o0;
        *(float4*)&g_ES[v * 64 + dg * 8 + 4] = o1;
    }
}

// ---------------------------------------------------------------------------
// Kernel 2: per-batch dynamic routing. One CTA per batch row, 256 threads.
// ---------------------------------------------------------------------------
__global__ __launch_bounds__(256) void k_route(const int* __restrict__ his,
                                               const float* __restrict__ B0) {
    extern __shared__ float sm[];
    float* hisP = sm;                              // 200*68
    float* Bk   = hisP + LSEQ * HPS;               // 4*200
    float* Wk   = Bk + 4 * LSEQ;                   // 4*200
    float* caps = Wk + 4 * LSEQ;                   // 4*64
    int*   idx  = (int*)(caps + 4 * 64);           // 200

    const int tid  = threadIdx.x;
    const int b    = blockIdx.x;
    const int lane = tid & 31;
    const int w    = tid >> 5;
    const float DROPV = -2147483648.0f;

    for (int l = tid; l < LSEQ; l += 256) idx[l] = his[b * LSEQ + l];
    for (int t = tid; t < 4 * LSEQ; t += 256) Bk[t] = B0[t];
    __syncthreads();

    // Gather hisP rows from precomputed ES (float4, 256B per row)
    for (int t = tid; t < LSEQ * 16; t += 256) {
        int l = t >> 4, d4 = t & 15;
        float4 v = ((const float4*)g_ES)[(size_t)idx[l] * 16 + d4];
        *(float4*)(hisP + l * HPS + d4 * 4) = v;
    }
    __syncthreads();

    for (int it = 0; it < 3; it++) {
        // ---- masked softmax over L, warps 0..3 handle k = w ----
        if (w < 4) {
            int k = w;
            float m = -FLT_MAX;
            for (int l = lane; l < LSEQ; l += 32) {
                float v = (idx[l] != 0) ? Bk[k * LSEQ + l] : DROPV;
                m = fmaxf(m, v);
            }
#pragma unroll
            for (int o = 16; o > 0; o >>= 1) m = fmaxf(m, __shfl_xor_sync(0xffffffffu, m, o));
            float s = 0.f;
            for (int l = lane; l < LSEQ; l += 32) {
                float v = (idx[l] != 0) ? Bk[k * LSEQ + l] : DROPV;
                float e = expf(v - m);
                Wk[k * LSEQ + l] = e;
                s += e;
            }
#pragma unroll
            for (int o = 16; o > 0; o >>= 1) s += __shfl_xor_sync(0xffffffffu, s, o);
            float inv = 1.f / s;
            for (int l = lane; l < LSEQ; l += 32) Wk[k * LSEQ + l] *= inv;
        }
        caps[tid] = 0.f;   // 4*64 == 256
        __syncthreads();

        // ---- caps[k][d] = sum_l W[k][l] * hisP[l][d] ----
        {
            const int d4 = tid & 15;        // 16 float4 columns
            const int lg = tid >> 4;        // 16 L-chunks of 13
            float4 a0 = make_float4(0, 0, 0, 0), a1 = a0, a2 = a0, a3 = a0;
            int l0 = lg * 13;
            int l1 = min(LSEQ, l0 + 13);
            for (int l = l0; l < l1; l++) {
                float4 h = *(float4*)(hisP + l * HPS + d4 * 4);
                float w0 = Wk[0 * LSEQ + l], w1 = Wk[1 * LSEQ + l];
                float w2 = Wk[2 * LSEQ + l], w3 = Wk[3 * LSEQ + l];
                a0.x = fmaf(w0, h.x, a0.x); a0.y = fmaf(w0, h.y, a0.y);
                a0.z = fmaf(w0, h.z, a0.z); a0.w = fmaf(w0, h.w, a0.w);
                a1.x = fmaf(w1, h.x, a1.x); a1.y = fmaf(w1, h.y, a1.y);
                a1.z = fmaf(w1, h.z, a1.z); a1.w = fmaf(w1, h.w, a1.w);
                a2.x = fmaf(w2, h.x, a2.x); a2.y = fmaf(w2, h.y, a2.y);
                a2.z = fmaf(w2, h.z, a2.z); a2.w = fmaf(w2, h.w, a2.w);
                a3.x = fmaf(w3, h.x, a3.x); a3.y = fmaf(w3, h.y, a3.y);
                a3.z = fmaf(w3, h.z, a3.z); a3.w = fmaf(w3, h.w, a3.w);
            }
            atomicAdd(&caps[0 * 64 + d4 * 4 + 0], a0.x);
            atomicAdd(&caps[0 * 64 + d4 * 4 + 1], a0.y);
            atomicAdd(&caps[0 * 64 + d4 * 4 + 2], a0.z);
            atomicAdd(&caps[0 * 64 + d4 * 4 + 3], a0.w);
            atomicAdd(&caps[1 * 64 + d4 * 4 + 0], a1.x);
            atomicAdd(&caps[1 * 64 + d4 * 4 + 1], a1.y);
            atomicAdd(&caps[1 * 64 + d4 * 4 + 2], a1.z);
            atomicAdd(&caps[1 * 64 + d4 * 4 + 3], a1.w);
            atomicAdd(&caps[2 * 64 + d4 * 4 + 0], a2.x);
            atomicAdd(&caps[2 * 64 + d4 * 4 + 1], a2.y);
            atomicAdd(&caps[2 * 64 + d4 * 4 + 2], a2.z);
            atomicAdd(&caps[2 * 64 + d4 * 4 + 3], a2.w);
            atomicAdd(&caps[3 * 64 + d4 * 4 + 0], a3.x);
            atomicAdd(&caps[3 * 64 + d4 * 4 + 1], a3.y);
            atomicAdd(&caps[3 * 64 + d4 * 4 + 2], a3.z);
            atomicAdd(&caps[3 * 64 + d4 * 4 + 3], a3.w);
        }
        __syncthreads();

        // ---- squash(caps), warps 0..3 handle k = w ----
        if (w < 4) {
            float x = caps[w * 64 + lane];
            float y = caps[w * 64 + 32 + lane];
            float ss = x * x + y * y;
#pragma unroll
            for (int o = 16; o > 0; o >>= 1) ss += __shfl_xor_sync(0xffffffffu, ss, o);
            float n2 = ss;
            float n = sqrtf(n2);
            float scale = n2 / ((1.f + n2) * n + 1e-9f);
            caps[w * 64 + lane]      = x * scale;
            caps[w * 64 + 32 + lane] = y * scale;
        }
        __syncthreads();

        if (it == 2) break;

        // ---- B[k][l] += dot(caps[k], hisP[l]) ----
        if (tid < LSEQ) {
            const int l = tid;
            float s0 = 0, s1 = 0, s2 = 0, s3 = 0;
#pragma unroll
            for (int d4 = 0; d4 < 16; d4++) {
                float4 h  = *(float4*)(hisP + l * HPS + d4 * 4);
                float4 c0 = *(float4*)(caps + 0 * 64 + d4 * 4);
                float4 c1 = *(float4*)(caps + 1 * 64 + d4 * 4);
                float4 c2 = *(float4*)(caps + 2 * 64 + d4 * 4);
                float4 c3 = *(float4*)(caps + 3 * 64 + d4 * 4);
                s0 += h.x * c0.x + h.y * c0.y + h.z * c0.z + h.w * c0.w;
                s1 += h.x * c1.x + h.y * c1.y + h.z * c1.z + h.w * c1.w;
                s2 += h.x * c2.x + h.y * c2.y + h.z * c2.z + h.w * c2.w;
                s3 += h.x * c3.x + h.y * c3.y + h.z * c3.z + h.w * c3.w;
            }
            Bk[0 * LSEQ + l] += s0;
            Bk[1 * LSEQ + l] += s1;
            Bk[2 * LSEQ + l] += s2;
            Bk[3 * LSEQ + l] += s3;
        }
        __syncthreads();
    }

    // write caps (k*64+d layout matches (b,k,d) row-major)
    g_caps[b * 256 + tid] = caps[tid];
}

// ---------------------------------------------------------------------------
// Kernel 3: batched MLP. rows = BS*K = 16384. Per block: 64 rows.
// h = relu(caps @ W1 + b1); out = h @ W2 + b2
// ---------------------------------------------------------------------------
__global__ __launch_bounds__(256) void k_mlp(const float* __restrict__ W1,
                                             const float* __restrict__ b1,
                                             const float* __restrict__ W2,
                                             const float* __restrict__ b2,
                                             float* __restrict__ out) {
    extern __shared__ float sm[];
    float* W1s = sm;                     // 64*256
    float* W2s = W1s + 64 * 256;         // 256*64
    float* hs  = W2s + 256 * 64;         // 64*260 (pad)
    float* cs  = hs + 64 * 260;          // 64*64
    float* b1s = cs + 64 * 64;           // 256
    float* b2s = b1s + 256;              // 64
    const int tid = threadIdx.x;
    const int row0 = blockIdx.x * 64;

    for (int i = tid; i < 64 * 256; i += 256) W1s[i] = W1[i];
    for (int i = tid; i < 256 * 64; i += 256) W2s[i] = W2[i];
    for (int i = tid; i < 64 * 64; i += 256) cs[i] = g_caps[row0 * 64 + i];
    if (tid < 256) b1s[tid] = b1[tid];
    if (tid < 64)  b2s[tid] = b2[tid];
    __syncthreads();

    // GEMM1 + bias + relu: h[64][256]
    {
        const int rg = tid >> 5;   // 0..7, 8 rows each
        const int fq = tid & 31;   // 0..31, f = fq + 32*c
        float acc[8][8];
#pragma unroll
        for (int r = 0; r < 8; r++)
#pragma unroll
            for (int c = 0; c < 8; c++) acc[r][c] = 0.f;

#pragma unroll 2
        for (int e = 0; e < 64; e++) {
            float cv[8], wv[8];
#pragma unroll
            for (int r = 0; r < 8; r++) cv[r] = cs[(rg * 8 + r) * 64 + e];
#pragma unroll
            for (int c = 0; c < 8; c++) wv[c] = W1s[e * 256 + fq + 32 * c];
#pragma unroll
            for (int r = 0; r < 8; r++)
#pragma unroll
                for (int c = 0; c < 8; c++) acc[r][c] = fmaf(cv[r], wv[c], acc[r][c]);
        }
#pragma unroll
        for (int r = 0; r < 8; r++)
#pragma unroll
            for (int c = 0; c < 8; c++) {
                float h = acc[r][c] + b1s[fq + 32 * c];
                hs[(rg * 8 + r) * 260 + fq + 32 * c] = fmaxf(h, 0.f);
            }
    }
    __syncthreads();

    // GEMM2 + bias: out[64][64]
    {
        const int rq = tid >> 4;   // 0..15, 4 rows each
        const int dq = tid & 15;   // 0..15, 4 cols each (contiguous -> float4)
        float acc[4][4];
#pragma unroll
        for (int i = 0; i < 4; i++)
#pragma unroll
            for (int j = 0; j < 4; j++) acc[i][j] = 0.f;

#pragma unroll 2
        for (int f = 0; f < 256; f++) {
            float hv[4];
#pragma unroll
            for (int i = 0; i < 4; i++) hv[i] = hs[(rq * 4 + i) * 260 + f];
            float4 wv = *(float4*)&W2s[f * 64 + dq * 4];
#pragma unroll
            for (int i = 0; i < 4; i++) {
                acc[i][0] = fmaf(hv[i], wv.x, acc[i][0]);
                acc[i][1] = fmaf(hv[i], wv.y, acc[i][1]);
                acc[i][2] = fmaf(hv[i], wv.z, acc[i][2]);
                acc[i][3] = fmaf(hv[i], wv.w, acc[i][3]);
            }
        }
        float4 bb = *(float4*)&b2s[dq * 4];
#pragma unroll
        for (int i = 0; i < 4; i++) {
            float4 o;
            o.x = acc[i][0] + bb.x;
            o.y = acc[i][1] + bb.y;
            o.z = acc[i][2] + bb.z;
            o.w = acc[i][3] + bb.w;
            *(float4*)&out[(size_t)(row0 + rq * 4 + i) * 64 + dq * 4] = o;
        }
    }
}

// ---------------------------------------------------------------------------
static const int SMEM1 = (64 * 64 + 256 * 65) * 4;                         // 82,944 B
static const int SMEM2 = (LSEQ * HPS + 4 * LSEQ * 2 + 4 * 64) * 4 + LSEQ * 4; // 62,624 B
static const int SMEM3 = (64 * 256 + 256 * 64 + 64 * 260 + 64 * 64 + 256 + 64) * 4; // 215,296 B

extern "C" void kernel_launch(void* const* d_in, const int* in_sizes, int n_in,
                              void* d_out, int out_size) {
    const int*   his = (const int*)  d_in[0];
    const float* E   = (const float*)d_in[1];
    const float* S   = (const float*)d_in[2];
    const float* B0  = (const float*)d_in[3];
    const float* W1  = (const float*)d_in[4];
    const float* b1  = (const float*)d_in[5];
    const float* W2  = (const float*)d_in[6];
    const float* b2  = (const float*)d_in[7];
    float* out = (float*)d_out;

    cudaFuncSetAttribute(k_es,    cudaFuncAttributeMaxDynamicSharedMemorySize, SMEM1);
    cudaFuncSetAttribute(k_route, cudaFuncAttributeMaxDynamicSharedMemorySize, SMEM2);
    cudaFuncSetAttribute(k_mlp,   cudaFuncAttributeMaxDynamicSharedMemorySize, SMEM3);

    k_es<<<(VOCAB + 255) / 256, 256, SMEM1>>>(E, S);
    k_route<<<BS, 256, SMEM2>>>(his, B0);
    k_mlp<<<(BS * KCAPS) / 64, 256, SMEM3>>>(W1, b1, W2, b2, out);
}

// round 2
// speedup vs baseline: 1.3407x; 1.3407x over previous
#include <cuda_runtime.h>
#include <math.h>
#include <float.h>

#define BS    4096
#define LSEQ  200
#define KCAPS 4
#define VOCAB 100000
#define HPS   65   // odd stride -> conflict-free scalar LDS in both l- and d-major patterns

// Scratch (allocation-free: device globals)
__device__ float g_ES[VOCAB * 64];            // 25.6 MB: E @ S, row 0 zeroed
__device__ float g_caps[BS * KCAPS * 64];     // 4 MB: routing output

// ---------------------------------------------------------------------------
// Kernel 1: ES = E @ S  (100000x64 @ 64x64), ES[0,:] = 0
// 256 threads, 128 rows/CTA, per-thread 8x4 tile. 49.7KB smem -> 4 CTAs/SM.
// ---------------------------------------------------------------------------
__global__ __launch_bounds__(256) void k_es(const float* __restrict__ E,
                                            const float* __restrict__ S) {
    extern __shared__ float sm[];
    float* Ssm = sm;                 // 64*64
    float* Esm = sm + 4096;          // 128*65
    const int tid = threadIdx.x;
    const int v0 = blockIdx.x * 128;

    for (int i = tid; i < 1024; i += 256)
        ((float4*)Ssm)[i] = ((const float4*)S)[i];
    // stage E rows (coalesced LDG.128, ~2-way STS conflicts)
    for (int i = tid; i < 2048; i += 256) {       // 128 rows * 16 float4
        int r = i >> 4, e4 = i & 15;
        int v = v0 + r;
        float4 val = make_float4(0.f, 0.f, 0.f, 0.f);
        if (v < VOCAB) val = *(const float4*)&E[(size_t)v * 64 + e4 * 4];
        float* p = &Esm[r * HPS + e4 * 4];
        p[0] = val.x; p[1] = val.y; p[2] = val.z; p[3] = val.w;
    }
    __syncthreads();

    const int vg = tid >> 4;   // 16 groups x 8 rows
    const int dg = tid & 15;   // 16 groups x 4 cols
    float acc[8][4];
#pragma unroll
    for (int r = 0; r < 8; r++)
#pragma unroll
        for (int c = 0; c < 4; c++) acc[r][c] = 0.f;

#pragma unroll 4
    for (int e = 0; e < 64; e++) {
        float4 sv = *(float4*)&Ssm[e * 64 + dg * 4];
        float Ev[8];
#pragma unroll
        for (int r = 0; r < 8; r++) Ev[r] = Esm[(vg * 8 + r) * HPS + e];
#pragma unroll
        for (int r = 0; r < 8; r++) {
            acc[r][0] = fmaf(Ev[r], sv.x, acc[r][0]);
            acc[r][1] = fmaf(Ev[r], sv.y, acc[r][1]);
            acc[r][2] = fmaf(Ev[r], sv.z, acc[r][2]);
            acc[r][3] = fmaf(Ev[r], sv.w, acc[r][3]);
        }
    }

#pragma unroll
    for (int r = 0; r < 8; r++) {
        int v = v0 + vg * 8 + r;
        if (v >= VOCAB) continue;
        float4 o = make_float4(acc[r][0], acc[r][1], acc[r][2], acc[r][3]);
        if (v == 0) o = make_float4(0.f, 0.f, 0.f, 0.f);   // padding_idx row
        *(float4*)&g_ES[(size_t)v * 64 + dg * 4] = o;
    }
}

// ---------------------------------------------------------------------------
// Kernel 2: per-batch dynamic routing. One CTA per batch row, 256 threads.
// No atomics; all smem access conflict-free or broadcast.
// ---------------------------------------------------------------------------
__global__ __launch_bounds__(256) void k_route(const int* __restrict__ his,
                                               const float* __restrict__ B0) {
    extern __shared__ float sm[];
    float* hisP  = sm;                       // 200*65 = 13000
    float* Bk    = hisP + LSEQ * HPS;        // 4*200 [k][l]
    float* WkT   = Bk + 4 * LSEQ;            // 200*4 [l][k]  (unnormalized exp)
    float* capsT = WkT + 4 * LSEQ;           // 64*4  [d][k]
    float* part  = capsT + 256;              // 4*256 partial caps
    float* nrm   = part + 1024;              // 8 warp norm partials
    float* invs  = nrm + 8;                  // 4 softmax 1/sum
    int*   idx   = (int*)(invs + 4);         // 200

    const int tid  = threadIdx.x;
    const int b    = blockIdx.x;
    const int lane = tid & 31;
    const int w    = tid >> 5;
    const int k    = tid >> 6;    // 0..3
    const int dd   = tid & 63;    // 0..63
    const float DROPV = -2147483648.0f;

    for (int l = tid; l < LSEQ; l += 256) idx[l] = his[b * LSEQ + l];
    for (int t = tid; t < 4 * LSEQ; t += 256) Bk[t] = B0[t];
    __syncthreads();

    // Gather hisP rows from precomputed ES
    for (int t = tid; t < LSEQ * 16; t += 256) {
        int l = t >> 4, d4 = t & 15;
        float4 v = ((const float4*)g_ES)[(size_t)idx[l] * 16 + d4];
        float* p = hisP + l * HPS + d4 * 4;
        p[0] = v.x; p[1] = v.y; p[2] = v.z; p[3] = v.w;
    }
    __syncthreads();

    for (int it = 0; it < 3; it++) {
        // ---- masked softmax over L, warps 0..3 handle k = w; store exp + 1/sum ----
        if (w < 4) {
            float m = -FLT_MAX;
            for (int l = lane; l < LSEQ; l += 32) {
                float v = (idx[l] != 0) ? Bk[w * LSEQ + l] : DROPV;
                m = fmaxf(m, v);
            }
#pragma unroll
            for (int o = 16; o > 0; o >>= 1) m = fmaxf(m, __shfl_xor_sync(0xffffffffu, m, o));
            float s = 0.f;
            for (int l = lane; l < LSEQ; l += 32) {
                float v = (idx[l] != 0) ? Bk[w * LSEQ + l] : DROPV;
                float e = __expf(v - m);
                WkT[l * 4 + w] = e;
                s += e;
            }
#pragma unroll
            for (int o = 16; o > 0; o >>= 1) s += __shfl_xor_sync(0xffffffffu, s, o);
            if (lane == 0) invs[w] = 1.f / s;
        }
        __syncthreads();

        // ---- caps partials: thread (lc, d) accumulates all 4 k over 50 l ----
        {
            const int lc = tid >> 6;     // 0..3 l-chunk
            const int d  = tid & 63;
            float a0 = 0.f, a1 = 0.f, a2 = 0.f, a3 = 0.f;
            const int l0 = lc * 50;
#pragma unroll 2
            for (int l = l0; l < l0 + 50; l++) {
                float  h  = hisP[l * HPS + d];
                float4 w4 = *(const float4*)&WkT[l * 4];   // broadcast
                a0 = fmaf(w4.x, h, a0);
                a1 = fmaf(w4.y, h, a1);
                a2 = fmaf(w4.z, h, a2);
                a3 = fmaf(w4.w, h, a3);
            }
            part[lc * 256 +   0 + d] = a0;
            part[lc * 256 +  64 + d] = a1;
            part[lc * 256 + 128 + d] = a2;
            part[lc * 256 + 192 + d] = a3;
        }
        __syncthreads();

        // ---- reduce partials, apply 1/sum, squash ----
        float c = part[tid] + part[256 + tid] + part[512 + tid] + part[768 + tid];
        c *= invs[k];
        float sq = c * c;
#pragma unroll
        for (int o = 16; o > 0; o >>= 1) sq += __shfl_xor_sync(0xffffffffu, sq, o);
        if (lane == 0) nrm[w] = sq;
        __syncthreads();
        float n2 = nrm[2 * k] + nrm[2 * k + 1];
        float n  = sqrtf(n2);
        float scale = n2 / ((1.f + n2) * n + 1e-9f);
        float cv = c * scale;

        if (it == 2) {
            g_caps[b * 256 + tid] = cv;     // tid = k*64+d matches (b,k,d)
            break;
        }
        capsT[dd * 4 + k] = cv;
        __syncthreads();

        // ---- B[k][l] += dot(caps[k], hisP[l]) : thread-per-l, all 4 k ----
        if (tid < LSEQ) {
            const int l = tid;
            float s0 = 0.f, s1 = 0.f, s2 = 0.f, s3 = 0.f;
#pragma unroll 8
            for (int d = 0; d < 64; d++) {
                float  h  = hisP[l * HPS + d];
                float4 c4 = *(const float4*)&capsT[d * 4];   // broadcast
                s0 = fmaf(h, c4.x, s0);
                s1 = fmaf(h, c4.y, s1);
                s2 = fmaf(h, c4.z, s2);
                s3 = fmaf(h, c4.w, s3);
            }
            Bk[0 * LSEQ + l] += s0;
            Bk[1 * LSEQ + l] += s1;
            Bk[2 * LSEQ + l] += s2;
            Bk[3 * LSEQ + l] += s3;
        }
        __syncthreads();
    }
}

// ---------------------------------------------------------------------------
// Kernel 3: batched MLP, f-chunked (4 chunks of 64). 68KB smem -> 3 CTAs/SM.
// ---------------------------------------------------------------------------
__global__ __launch_bounds__(256) void k_mlp(const float* __restrict__ W1,
                                             const float* __restrict__ b1,
                                             const float* __restrict__ W2,
                                             const float* __restrict__ b2,
                                             float* __restrict__ out) {
    extern __shared__ float sm[];
    float* W1c = sm;                 // 64*64 (e x f-chunk)
    float* W2c = W1c + 4096;         // 64*64 (f-chunk x d)
    float* cs  = W2c + 4096;         // 64*65 caps rows (padded)
    float* hs  = cs + 64 * 65;       // 64*68 h chunk (padded)
    float* b1s = hs + 64 * 68;       // 256
    float* b2s = b1s + 256;          // 64
    const int tid  = threadIdx.x;
    const int row0 = blockIdx.x * 64;

    for (int i = tid; i < 4096; i += 256) {
        int r = i >> 6, e = i & 63;
        cs[r * 65 + e] = g_caps[row0 * 64 + i];
    }
    if (tid < 256) b1s[tid] = b1[tid];
    if (tid < 64)  b2s[tid] = b2[tid];

    const int rq = tid >> 4;   // 16 groups x 4 rows
    const int dq = tid & 15;   // 16 groups x 4 cols/f
    float acc2[4][4];
#pragma unroll
    for (int i = 0; i < 4; i++)
#pragma unroll
        for (int j = 0; j < 4; j++) acc2[i][j] = 0.f;

    for (int ch = 0; ch < 4; ch++) {
        const int f0 = ch * 64;
        __syncthreads();   // previous GEMM2 done with W2c/hs; cs/b1s ready on first pass
        for (int i4 = tid; i4 < 1024; i4 += 256) {
            int e = i4 >> 4, j4 = i4 & 15;
            ((float4*)W1c)[i4] = *(const float4*)&W1[e * 256 + f0 + j4 * 4];
        }
        for (int i4 = tid; i4 < 1024; i4 += 256)
            ((float4*)W2c)[i4] = ((const float4*)&W2[f0 * 64])[i4];
        __syncthreads();

        // GEMM1: h[64][64] = cs @ W1c (+b1, relu)
        {
            float acc1[4][4];
#pragma unroll
            for (int i = 0; i < 4; i++)
#pragma unroll
                for (int j = 0; j < 4; j++) acc1[i][j] = 0.f;
#pragma unroll 4
            for (int e = 0; e < 64; e++) {
                float cv[4];
#pragma unroll
                for (int i = 0; i < 4; i++) cv[i] = cs[(rq * 4 + i) * 65 + e];
                float4 wv = *(float4*)&W1c[e * 64 + dq * 4];
#pragma unroll
                for (int i = 0; i < 4; i++) {
                    acc1[i][0] = fmaf(cv[i], wv.x, acc1[i][0]);
                    acc1[i][1] = fmaf(cv[i], wv.y, acc1[i][1]);
                    acc1[i][2] = fmaf(cv[i], wv.z, acc1[i][2]);
                    acc1[i][3] = fmaf(cv[i], wv.w, acc1[i][3]);
                }
            }
            float4 bb = *(float4*)&b1s[f0 + dq * 4];
#pragma unroll
            for (int i = 0; i < 4; i++) {
                float4 h;
                h.x = fmaxf(acc1[i][0] + bb.x, 0.f);
                h.y = fmaxf(acc1[i][1] + bb.y, 0.f);
                h.z = fmaxf(acc1[i][2] + bb.z, 0.f);
                h.w = fmaxf(acc1[i][3] + bb.w, 0.f);
                *(float4*)&hs[(rq * 4 + i) * 68 + dq * 4] = h;
            }
        }
        __syncthreads();

        // GEMM2 accumulate: out[64][64] += h_chunk @ W2c
#pragma unroll 4
        for (int f = 0; f < 64; f++) {
            float hv[4];
#pragma unroll
            for (int i = 0; i < 4; i++) hv[i] = hs[(rq * 4 + i) * 68 + f];
            float4 wv = *(float4*)&W2c[f * 64 + dq * 4];
#pragma unroll
            for (int i = 0; i < 4; i++) {
                acc2[i][0] = fmaf(hv[i], wv.x, acc2[i][0]);
                acc2[i][1] = fmaf(hv[i], wv.y, acc2[i][1]);
                acc2[i][2] = fmaf(hv[i], wv.z, acc2[i][2]);
                acc2[i][3] = fmaf(hv[i], wv.w, acc2[i][3]);
            }
        }
    }

    float4 bb = *(float4*)&b2s[dq * 4];
#pragma unroll
    for (int i = 0; i < 4; i++) {
        float4 o;
        o.x = acc2[i][0] + bb.x;
        o.y = acc2[i][1] + bb.y;
        o.z = acc2[i][2] + bb.z;
        o.w = acc2[i][3] + bb.w;
        *(float4*)&out[(size_t)(row0 + rq * 4 + i) * 64 + dq * 4] = o;
    }
}

// ---------------------------------------------------------------------------
static const int SMEM1 = (4096 + 128 * HPS) * 4;                                  // 49,664 B
static const int SMEM2 = (LSEQ * HPS + 8 * LSEQ + 256 + 1024 + 8 + 4) * 4 + LSEQ * 4; // ~64.4 KB
static const int SMEM3 = (4096 + 4096 + 64 * 65 + 64 * 68 + 256 + 64) * 4;        // 68,096 B

extern "C" void kernel_launch(void* const* d_in, const int* in_sizes, int n_in,
                              void* d_out, int out_size) {
    const int*   his = (const int*)  d_in[0];
    const float* E   = (const float*)d_in[1];
    const float* S   = (const float*)d_in[2];
    const float* B0  = (const float*)d_in[3];
    const float* W1  = (const float*)d_in[4];
    const float* b1  = (const float*)d_in[5];
    const float* W2  = (const float*)d_in[6];
    const float* b2  = (const float*)d_in[7];
    float* out = (float*)d_out;

    cudaFuncSetAttribute(k_es,    cudaFuncAttributeMaxDynamicSharedMemorySize, SMEM1);
    cudaFuncSetAttribute(k_route, cudaFuncAttributeMaxDynamicSharedMemorySize, SMEM2);
    cudaFuncSetAttribute(k_mlp,   cudaFuncAttributeMaxDynamicSharedMemorySize, SMEM3);

    k_es<<<(VOCAB + 127) / 128, 256, SMEM1>>>(E, S);
    k_route<<<BS, 256, SMEM2>>>(his, B0);
    k_mlp<<<(BS * KCAPS) / 64, 256, SMEM3>>>(W1, b1, W2, b2, out);
}

// round 3
// speedup vs baseline: 1.4282x; 1.0653x over previous
#include <cuda_runtime.h>
#include <math.h>
#include <float.h>

#define BS    4096
#define LSEQ  200
#define KCAPS 4
#define VOCAB 100000
#define HPS   65   // k_es Esm stride
#define HPR   66   // route hisP stride (even -> 8B-aligned pairs, 2-way worst conflicts)

typedef unsigned long long u64;

// ---- packed fp32x2 helpers (Blackwell FFMA2 path) ----
__device__ __forceinline__ u64 pack2(float x, float y) {
    u64 r; asm("mov.b64 %0, {%1, %2};" : "=l"(r) : "f"(x), "f"(y)); return r;
}
__device__ __forceinline__ u64 pack_dup(float x) {
    u64 r; asm("mov.b64 %0, {%1, %1};" : "=l"(r) : "f"(x)); return r;
}
__device__ __forceinline__ void unpack2(u64 v, float& x, float& y) {
    asm("mov.b64 {%0, %1}, %2;" : "=f"(x), "=f"(y) : "l"(v));
}
__device__ __forceinline__ void ffma2(u64& d, u64 a, u64 b) {
    asm("fma.rn.f32x2 %0, %1, %2, %0;" : "+l"(d) : "l"(a), "l"(b));
}
__device__ __forceinline__ u64 fadd2(u64 a, u64 b) {
    u64 r; asm("add.rn.f32x2 %0, %1, %2;" : "=l"(r) : "l"(a), "l"(b)); return r;
}

// Scratch (allocation-free: device globals)
__device__ float g_ES[VOCAB * 64];            // 25.6 MB: E @ S, row 0 zeroed
__device__ float g_caps[BS * KCAPS * 64];     // 4 MB: routing output

// ---------------------------------------------------------------------------
// Kernel 1: ES = E @ S, packed FFMA2. 128 rows/CTA, thread tile 8x(2 pairs).
// ---------------------------------------------------------------------------
__global__ __launch_bounds__(256) void k_es(const float* __restrict__ E,
                                            const float* __restrict__ S) {
    extern __shared__ float sm[];
    float* Ssm = sm;                 // 64*64
    float* Esm = sm + 4096;          // 128*65
    const int tid = threadIdx.x;
    const int v0 = blockIdx.x * 128;

    for (int i = tid; i < 1024; i += 256)
        ((float4*)Ssm)[i] = ((const float4*)S)[i];
    for (int i = tid; i < 2048; i += 256) {       // 128 rows * 16 float4
        int r = i >> 4, e4 = i & 15;
        int v = v0 + r;
        float4 val = make_float4(0.f, 0.f, 0.f, 0.f);
        if (v < VOCAB) val = *(const float4*)&E[(size_t)v * 64 + e4 * 4];
        float* p = &Esm[r * HPS + e4 * 4];
        p[0] = val.x; p[1] = val.y; p[2] = val.z; p[3] = val.w;
    }
    __syncthreads();

    const int vg = tid >> 4;   // 16 groups x 8 rows
    const int dg = tid & 15;   // 16 groups x 4 cols (2 pairs)
    u64 acc[8][2];
#pragma unroll
    for (int r = 0; r < 8; r++) { acc[r][0] = 0ull; acc[r][1] = 0ull; }

#pragma unroll 4
    for (int e = 0; e < 64; e++) {
        ulonglong2 sv = *(ulonglong2*)&Ssm[e * 64 + dg * 4];   // (S[e][c0..3]) packed
        u64 ed[8];
#pragma unroll
        for (int r = 0; r < 8; r++) ed[r] = pack_dup(Esm[(vg * 8 + r) * HPS + e]);
#pragma unroll
        for (int r = 0; r < 8; r++) {
            ffma2(acc[r][0], ed[r], sv.x);
            ffma2(acc[r][1], ed[r], sv.y);
        }
    }

#pragma unroll
    for (int r = 0; r < 8; r++) {
        int v = v0 + vg * 8 + r;
        if (v >= VOCAB) continue;
        float4 o;
        unpack2(acc[r][0], o.x, o.y);
        unpack2(acc[r][1], o.z, o.w);
        if (v == 0) o = make_float4(0.f, 0.f, 0.f, 0.f);   // padding_idx row
        *(float4*)&g_ES[(size_t)v * 64 + dg * 4] = o;
    }
}

// ---------------------------------------------------------------------------
// Kernel 2: per-batch dynamic routing, packed FFMA2 hot loops, no atomics.
// One CTA per batch row, 256 threads.
// ---------------------------------------------------------------------------
__global__ __launch_bounds__(256) void k_route(const int* __restrict__ his,
                                               const float* __restrict__ B0) {
    extern __shared__ u64 smu[];
    u64*   part2 = smu;                    // [8 lc][k*32+dp] = 1024 u64
    u64*   WkT2  = part2 + 1024;           // [l][k] dup-packed exp = 800 u64
    u64*   capsS = WkT2 + 800;             // [k*32+dp] packed caps = 128 u64
    float* hisP  = (float*)(capsS + 128);  // 200*66 floats (8B-aligned pairs)
    float* Bk    = hisP + LSEQ * HPR;      // [k][l] 800
    float* invs  = Bk + 4 * LSEQ;          // 4
    int*   idx   = (int*)(invs + 4);       // 200

    const int tid  = threadIdx.x;
    const int b    = blockIdx.x;
    const int lane = tid & 31;
    const int w    = tid >> 5;
    const float DROPV = -2147483648.0f;

    for (int l = tid; l < LSEQ; l += 256) idx[l] = his[b * LSEQ + l];
    for (int t = tid; t < 4 * LSEQ; t += 256) Bk[t] = B0[t];
    __syncthreads();

    // Gather hisP rows from precomputed ES (8B stores keep alignment w/ odd l)
    for (int t = tid; t < LSEQ * 16; t += 256) {
        int l = t >> 4, d4 = t & 15;
        float4 v = ((const float4*)g_ES)[(size_t)idx[l] * 16 + d4];
        float2* p = (float2*)&hisP[l * HPR + d4 * 4];
        p[0] = make_float2(v.x, v.y);
        p[1] = make_float2(v.z, v.w);
    }
    __syncthreads();

    for (int it = 0; it < 3; it++) {
        // ---- masked softmax over L, warps 0..3 handle k = w ----
        if (w < 4) {
            float m = -FLT_MAX;
            for (int l = lane; l < LSEQ; l += 32) {
                float v = (idx[l] != 0) ? Bk[w * LSEQ + l] : DROPV;
                m = fmaxf(m, v);
            }
#pragma unroll
            for (int o = 16; o > 0; o >>= 1) m = fmaxf(m, __shfl_xor_sync(0xffffffffu, m, o));
            float s = 0.f;
            for (int l = lane; l < LSEQ; l += 32) {
                float v = (idx[l] != 0) ? Bk[w * LSEQ + l] : DROPV;
                float e = __expf(v - m);
                WkT2[l * 4 + w] = pack_dup(e);
                s += e;
            }
#pragma unroll
            for (int o = 16; o > 0; o >>= 1) s += __shfl_xor_sync(0xffffffffu, s, o);
            if (lane == 0) invs[w] = 1.f / s;
        }
        __syncthreads();

        // ---- caps partials: thread (lc, dp) does 25 l, 4 k, 2 d (packed) ----
        {
            const int lc = tid >> 5;     // 0..7, 25 l each
            const int dp = tid & 31;     // d-pair
            u64 a0 = 0ull, a1 = 0ull, a2 = 0ull, a3 = 0ull;
            const int l0 = lc * 25;
#pragma unroll 5
            for (int l = l0; l < l0 + 25; l++) {
                u64 h2 = *(u64*)&hisP[l * HPR + 2 * dp];
                ulonglong2 w01 = *(ulonglong2*)&WkT2[l * 4];       // broadcast
                ulonglong2 w23 = *(ulonglong2*)&WkT2[l * 4 + 2];
                ffma2(a0, h2, w01.x);
                ffma2(a1, h2, w01.y);
                ffma2(a2, h2, w23.x);
                ffma2(a3, h2, w23.y);
            }
            part2[lc * 128 +  0 + dp] = a0;
            part2[lc * 128 + 32 + dp] = a1;
            part2[lc * 128 + 64 + dp] = a2;
            part2[lc * 128 + 96 + dp] = a3;
        }
        __syncthreads();

        // ---- reduce partials (tid<128: warp w = k, lane = dp), squash ----
        if (tid < 128) {
            const int k = tid >> 5;
            u64 c2 = part2[tid];
#pragma unroll
            for (int lc = 1; lc < 8; lc++) c2 = fadd2(c2, part2[lc * 128 + tid]);
            float cx, cy;
            unpack2(c2, cx, cy);
            float inv = invs[k];
            cx *= inv; cy *= inv;
            float sq = cx * cx + cy * cy;
#pragma unroll
            for (int o = 16; o > 0; o >>= 1) sq += __shfl_xor_sync(0xffffffffu, sq, o);
            float n2 = sq;
            float n  = sqrtf(n2);
            float scale = n2 / ((1.f + n2) * n + 1e-9f);
            cx *= scale; cy *= scale;
            if (it == 2) {
                *(float2*)&g_caps[b * 256 + 2 * tid] = make_float2(cx, cy);
            } else {
                capsS[tid] = pack2(cx, cy);
            }
        }
        if (it == 2) break;
        __syncthreads();

        // ---- B[k][l] += dot(caps[k], hisP[l]) : thread-per-l, packed ----
        if (tid < LSEQ) {
            const int l = tid;
            u64 s0 = 0ull, s1 = 0ull, s2 = 0ull, s3 = 0ull;
#pragma unroll 8
            for (int dp = 0; dp < 32; dp++) {
                u64 h2 = *(u64*)&hisP[l * HPR + 2 * dp];
                ffma2(s0, h2, capsS[dp]);
                ffma2(s1, h2, capsS[32 + dp]);
                ffma2(s2, h2, capsS[64 + dp]);
                ffma2(s3, h2, capsS[96 + dp]);
            }
            float x, y;
            unpack2(s0, x, y); Bk[0 * LSEQ + l] += x + y;
            unpack2(s1, x, y); Bk[1 * LSEQ + l] += x + y;
            unpack2(s2, x, y); Bk[2 * LSEQ + l] += x + y;
            unpack2(s3, x, y); Bk[3 * LSEQ + l] += x + y;
        }
        __syncthreads();
    }
}

// ---------------------------------------------------------------------------
// Kernel 3: batched MLP, f-chunked (4x64), packed FFMA2 in both GEMMs.
// ---------------------------------------------------------------------------
__global__ __launch_bounds__(256) void k_mlp(const float* __restrict__ W1,
                                             const float* __restrict__ b1,
                                             const float* __restrict__ W2,
                                             const float* __restrict__ b2,
                                             float* __restrict__ out) {
    extern __shared__ float sm[];
    float* W1c = sm;                 // 64*64 (e x f-chunk)
    float* W2c = W1c + 4096;         // 64*64 (f-chunk x d)
    float* cs  = W2c + 4096;         // 64*65 caps rows (padded)
    float* hs  = cs + 64 * 65;       // 64*68 h chunk (padded)
    float* b1s = hs + 64 * 68;       // 256
    float* b2s = b1s + 256;          // 64
    const int tid  = threadIdx.x;
    const int row0 = blockIdx.x * 64;

    for (int i = tid; i < 4096; i += 256) {
        int r = i >> 6, e = i & 63;
        cs[r * 65 + e] = g_caps[row0 * 64 + i];
    }
    if (tid < 256) b1s[tid] = b1[tid];
    if (tid < 64)  b2s[tid] = b2[tid];

    const int rq = tid >> 4;   // 16 groups x 4 rows
    const int dq = tid & 15;   // 16 groups x 4 cols (2 pairs)
    u64 acc2[4][2];
#pragma unroll
    for (int i = 0; i < 4; i++) { acc2[i][0] = 0ull; acc2[i][1] = 0ull; }

    for (int ch = 0; ch < 4; ch++) {
        const int f0 = ch * 64;
        __syncthreads();
        for (int i4 = tid; i4 < 1024; i4 += 256) {
            int e = i4 >> 4, j4 = i4 & 15;
            ((float4*)W1c)[i4] = *(const float4*)&W1[e * 256 + f0 + j4 * 4];
        }
        for (int i4 = tid; i4 < 1024; i4 += 256)
            ((float4*)W2c)[i4] = ((const float4*)&W2[f0 * 64])[i4];
        __syncthreads();

        // GEMM1: h[64][64] = cs @ W1c (+b1, relu)
        {
            u64 acc1[4][2];
#pragma unroll
            for (int i = 0; i < 4; i++) { acc1[i][0] = 0ull; acc1[i][1] = 0ull; }
#pragma unroll 4
            for (int e = 0; e < 64; e++) {
                u64 cd[4];
#pragma unroll
                for (int i = 0; i < 4; i++) cd[i] = pack_dup(cs[(rq * 4 + i) * 65 + e]);
                ulonglong2 wv = *(ulonglong2*)&W1c[e * 64 + dq * 4];
#pragma unroll
                for (int i = 0; i < 4; i++) {
                    ffma2(acc1[i][0], cd[i], wv.x);
                    ffma2(acc1[i][1], cd[i], wv.y);
                }
            }
            float4 bb = *(float4*)&b1s[f0 + dq * 4];
#pragma unroll
            for (int i = 0; i < 4; i++) {
                float4 h; float x, y;
                unpack2(acc1[i][0], x, y); h.x = fmaxf(x + bb.x, 0.f); h.y = fmaxf(y + bb.y, 0.f);
                unpack2(acc1[i][1], x, y); h.z = fmaxf(x + bb.z, 0.f); h.w = fmaxf(y + bb.w, 0.f);
                *(float4*)&hs[(rq * 4 + i) * 68 + dq * 4] = h;
            }
        }
        __syncthreads();

        // GEMM2 accumulate: out[64][64] += h_chunk @ W2c
#pragma unroll 4
        for (int f = 0; f < 64; f++) {
            u64 hd[4];
#pragma unroll
            for (int i = 0; i < 4; i++) hd[i] = pack_dup(hs[(rq * 4 + i) * 68 + f]);
            ulonglong2 wv = *(ulonglong2*)&W2c[f * 64 + dq * 4];
#pragma unroll
            for (int i = 0; i < 4; i++) {
                ffma2(acc2[i][0], hd[i], wv.x);
                ffma2(acc2[i][1], hd[i], wv.y);
            }
        }
    }

    float4 bb = *(float4*)&b2s[dq * 4];
#pragma unroll
    for (int i = 0; i < 4; i++) {
        float4 o; float x, y;
        unpack2(acc2[i][0], x, y); o.x = x + bb.x; o.y = y + bb.y;
        unpack2(acc2[i][1], x, y); o.z = x + bb.z; o.w = y + bb.w;
        *(float4*)&out[(size_t)(row0 + rq * 4 + i) * 64 + dq * 4] = o;
    }
}

// ---------------------------------------------------------------------------
static const int SMEM1 = (4096 + 128 * HPS) * 4;                               // 49,664 B
static const int SMEM2 = (1024 + 800 + 128) * 8 + (LSEQ * HPR + 4 * LSEQ + 4) * 4 + LSEQ * 4; // 72,432 B
static const int SMEM3 = (4096 + 4096 + 64 * 65 + 64 * 68 + 256 + 64) * 4;     // 68,096 B

extern "C" void kernel_launch(void* const* d_in, const int* in_sizes, int n_in,
                              void* d_out, int out_size) {
    const int*   his = (const int*)  d_in[0];
    const float* E   = (const float*)d_in[1];
    const float* S   = (const float*)d_in[2];
    const float* B0  = (const float*)d_in[3];
    const float* W1  = (const float*)d_in[4];
    const float* b1  = (const float*)d_in[5];
    const float* W2  = (const float*)d_in[6];
    const float* b2  = (const float*)d_in[7];
    float* out = (float*)d_out;

    cudaFuncSetAttribute(k_es,    cudaFuncAttributeMaxDynamicSharedMemorySize, SMEM1);
    cudaFuncSetAttribute(k_route, cudaFuncAttributeMaxDynamicSharedMemorySize, SMEM2);
    cudaFuncSetAttribute(k_mlp,   cudaFuncAttributeMaxDynamicSharedMemorySize, SMEM3);

    k_es<<<(VOCAB + 127) / 128, 256, SMEM1>>>(E, S);
    k_route<<<BS, 256, SMEM2>>>(his, B0);
    k_mlp<<<(BS * KCAPS) / 64, 256, SMEM3>>>(W1, b1, W2, b2, out);
}